// round 7
// baseline (speedup 1.0000x reference)
#include <cuda_runtime.h>
#include <cuda_bf16.h>
#include <math.h>

#define NN 50000
#define EE 300000
#define CC 256
#define HH 8
#define ND 256
#define SLCAP 16384

// ---------------- scratch (__device__ globals) ----------------
__device__ __nv_bfloat16 g_Kb[NN * CC];
__device__ __nv_bfloat16 g_Vb[NN * CC];
__device__ __nv_bfloat16 g_Qb[ND * CC];
__device__ __nv_bfloat16 g_W[3][CC * CC];   // 0=q, 1=k, 2=v  (layout [n_out][k])
__device__ float    g_sc[(size_t)EE * HH];  // per-(edge-position, head) scores
__device__ float    g_attn[ND * CC];
__device__ int      g_deg[NN];
__device__ int      g_dcnt[ND];
__device__ int      g_off[ND + 1];
__device__ int      g_cur[ND];
__device__ int      g_order[EE];            // SRC node id per sorted slot
__device__ unsigned g_F1[ND * 8], g_F2[ND * 8], g_F3[ND * 8];
__device__ int      g_slist[SLCAP];
__device__ int      g_snum;

// ---------------- init ----------------
__global__ void k_init(int n) {
    int i = blockIdx.x * blockDim.x + threadIdx.x;
    if (i < n)      g_deg[i] = 0;
    if (i < ND)     g_dcnt[i] = 0;
    if (i < ND * 8) g_F1[i] = 0u;
    if (i == 0)     g_snum = 0;
}

// ---------------- converts ----------------
__global__ void k_cvt_w(const float* __restrict__ Wq, const float* __restrict__ Wk,
                        const float* __restrict__ Wv) {
    int i = blockIdx.x * blockDim.x + threadIdx.x;
    if (i >= CC * CC) return;
    g_W[0][i] = __float2bfloat16(Wq[i]);
    g_W[1][i] = __float2bfloat16(Wk[i]);
    g_W[2][i] = __float2bfloat16(Wv[i]);
}

// ---------------- edge preprocessing: smem histogram ----------------
__global__ void __launch_bounds__(256) k_edge(const int* __restrict__ src,
                                              const int* __restrict__ dst, int E) {
    __shared__ int sh[ND];
    int t = threadIdx.x;
    sh[t] = 0;
    __syncthreads();
    int stride = gridDim.x * blockDim.x;
    for (int i = blockIdx.x * blockDim.x + t; i < E; i += stride) {
        int s = src[i], d = dst[i];
        atomicAdd(&g_deg[s], 1);
        atomicAdd_block(&sh[d], 1);
        if (s < ND) {
            atomicOr(&g_F1[d * 8 + (s >> 5)], 1u << (s & 31));
            int p = atomicAdd(&g_snum, 1);
            if (p < SLCAP) g_slist[p] = (s << 8) | d;
        }
    }
    __syncthreads();
    int c = sh[t];
    if (c) atomicAdd(&g_dcnt[t], c);
}

// ---------------- BFS (register-owner rows) + scan fused ----------------
__global__ void __launch_bounds__(256) k_bfs_scan() {
    __shared__ unsigned sF[ND * 8];
    __shared__ int sscan[ND];
    int t = threadIdx.x;
    for (int i = t; i < ND * 8; i += 256) sF[i] = g_F1[i];
    int n = g_snum; if (n > SLCAP) n = SLCAP;
    __syncthreads();

    unsigned r2[8];
    #pragma unroll
    for (int w = 0; w < 8; w++) r2[w] = 0u;
    int n4 = (n + 3) >> 2;
    const int4* sl4 = (const int4*)g_slist;
    for (int i = 0; i < n4; i++) {
        int4 pk4 = __ldg(&sl4[i]);
        int base4 = i * 4;
        #pragma unroll
        for (int q = 0; q < 4; q++) {
            int pk = (&pk4.x)[q];
            if (base4 + q < n && (pk & 255) == t) {
                int s = pk >> 8;
                #pragma unroll
                for (int w = 0; w < 8; w++) r2[w] |= sF[s * 8 + w];
            }
        }
    }
    __syncthreads();
    #pragma unroll
    for (int w = 0; w < 8; w++) { sF[t * 8 + w] = r2[w]; g_F2[t * 8 + w] = r2[w]; }
    __syncthreads();

    unsigned r3[8];
    #pragma unroll
    for (int w = 0; w < 8; w++) r3[w] = 0u;
    for (int i = 0; i < n4; i++) {
        int4 pk4 = __ldg(&sl4[i]);
        int base4 = i * 4;
        #pragma unroll
        for (int q = 0; q < 4; q++) {
            int pk = (&pk4.x)[q];
            if (base4 + q < n && (pk & 255) == t) {
                int s = pk >> 8;
                #pragma unroll
                for (int w = 0; w < 8; w++) r3[w] |= sF[s * 8 + w];
            }
        }
    }
    #pragma unroll
    for (int w = 0; w < 8; w++) g_F3[t * 8 + w] = r3[w];

    int my = g_dcnt[t];
    g_deg[t] += my;
    sscan[t] = my; __syncthreads();
    for (int o = 1; o < ND; o <<= 1) {
        int v = (t >= o) ? sscan[t - o] : 0;
        __syncthreads();
        sscan[t] += v;
        __syncthreads();
    }
    int ex = sscan[t] - my;
    g_off[t] = ex;
    g_cur[t] = ex;
    if (t == ND - 1) g_off[ND] = sscan[t];
}

// ---------------- scatter: two-phase, stores SRC id ----------------
__global__ void __launch_bounds__(256) k_scatter(const int* __restrict__ src,
                                                 const int* __restrict__ dst, int E) {
    __shared__ int sh_cnt[ND];
    __shared__ int sh_base[ND];
    __shared__ int sh_cur[ND];
    int t = threadIdx.x;
    int chunk = (E + gridDim.x - 1) / gridDim.x;
    int lo = blockIdx.x * chunk;
    int hi = lo + chunk; if (hi > E) hi = E;
    sh_cnt[t] = 0; sh_cur[t] = 0;
    __syncthreads();
    for (int i = lo + t; i < hi; i += 256)
        atomicAdd_block(&sh_cnt[dst[i]], 1);
    __syncthreads();
    int c = sh_cnt[t];
    sh_base[t] = c ? atomicAdd(&g_cur[t], c) : 0;
    __syncthreads();
    for (int i = lo + t; i < hi; i += 256) {
        int d = dst[i];
        int p = sh_base[d] + atomicAdd_block(&sh_cur[d], 1);
        g_order[p] = src[i];
    }
}

// ---------------- bf16 GEMM (R3-proven): fp32 A, register prefetch ----------------
__device__ __forceinline__ void mma16816(float* c, const unsigned* a, const unsigned* b) {
    asm volatile(
        "mma.sync.aligned.m16n8k16.row.col.f32.bf16.bf16.f32 "
        "{%0,%1,%2,%3},{%4,%5,%6,%7},{%8,%9},{%0,%1,%2,%3};\n"
        : "+f"(c[0]), "+f"(c[1]), "+f"(c[2]), "+f"(c[3])
        : "r"(a[0]), "r"(a[1]), "r"(a[2]), "r"(a[3]), "r"(b[0]), "r"(b[1]));
}

__global__ void __launch_bounds__(256) k_gemm(const float* __restrict__ A, int which,
                                              const float* __restrict__ bias,
                                              int M, int osel) {
    const int LDA = 40;
    __shared__ __nv_bfloat16 As[128 * 40];
    __shared__ __nv_bfloat16 Bs[64 * 40];
    const __nv_bfloat16* W = g_W[which];
    __nv_bfloat16* Out = (osel == 0) ? g_Kb : (osel == 1) ? g_Vb : g_Qb;

    int tid = threadIdx.x, lane = tid & 31, wid = tid >> 5;
    int wm = wid & 3, wn = wid >> 2;
    int bm0 = blockIdx.x * 128, bn0 = blockIdx.y * 64;

    float acc[2][4][4];
    #pragma unroll
    for (int i = 0; i < 2; i++)
        #pragma unroll
        for (int j = 0; j < 4; j++)
            #pragma unroll
            for (int k = 0; k < 4; k++) acc[i][j][k] = 0.f;

    int arow = tid >> 1, acol = (tid & 1) * 16;
    int brow = tid >> 2, bcol = (tid & 3) * 8;
    int gm = bm0 + arow;
    bool aval = gm < M;
    const float* agp = A + (size_t)gm * 256 + acol;
    const __nv_bfloat16* bgp = W + (size_t)(bn0 + brow) * 256 + bcol;

    float4 fa[4];
    uint4 vb;
    #pragma unroll
    for (int q = 0; q < 4; q++)
        fa[q] = aval ? ((const float4*)agp)[q] : make_float4(0.f, 0.f, 0.f, 0.f);
    vb = *(const uint4*)bgp;

    for (int k0 = 0; k0 < 256; k0 += 32) {
        __nv_bfloat162 pk[8];
        #pragma unroll
        for (int q = 0; q < 4; q++) {
            pk[2 * q]     = __floats2bfloat162_rn(fa[q].x, fa[q].y);
            pk[2 * q + 1] = __floats2bfloat162_rn(fa[q].z, fa[q].w);
        }
        *(uint4*)&As[arow * LDA + acol]     = *(uint4*)&pk[0];
        *(uint4*)&As[arow * LDA + acol + 8] = *(uint4*)&pk[4];
        *(uint4*)&Bs[brow * LDA + bcol]     = vb;
        __syncthreads();
        if (k0 + 32 < 256) {
            const float* ag2 = agp + k0 + 32;
            #pragma unroll
            for (int q = 0; q < 4; q++)
                fa[q] = aval ? ((const float4*)ag2)[q] : make_float4(0.f, 0.f, 0.f, 0.f);
            vb = *(const uint4*)(bgp + k0 + 32);
        }
        #pragma unroll
        for (int kk = 0; kk < 32; kk += 16) {
            unsigned a[2][4], b[4][2];
            #pragma unroll
            for (int mt = 0; mt < 2; mt++) {
                int r = wm * 32 + mt * 16 + (lane & 15);
                int c = kk + (lane >> 4) * 8;
                unsigned addr = (unsigned)__cvta_generic_to_shared(&As[r * LDA + c]);
                asm volatile("ldmatrix.sync.aligned.m8n8.x4.shared.b16 {%0,%1,%2,%3},[%4];"
                    : "=r"(a[mt][0]), "=r"(a[mt][1]), "=r"(a[mt][2]), "=r"(a[mt][3])
                    : "r"(addr));
            }
            #pragma unroll
            for (int p = 0; p < 2; p++) {
                int r = wn * 32 + (2 * p + (lane >> 4)) * 8 + (lane & 7);
                int c = kk + ((lane >> 3) & 1) * 8;
                unsigned addr = (unsigned)__cvta_generic_to_shared(&Bs[r * LDA + c]);
                unsigned r0, r1, r2, r3;
                asm volatile("ldmatrix.sync.aligned.m8n8.x4.shared.b16 {%0,%1,%2,%3},[%4];"
                    : "=r"(r0), "=r"(r1), "=r"(r2), "=r"(r3) : "r"(addr));
                b[2 * p][0] = r0; b[2 * p][1] = r1;
                b[2 * p + 1][0] = r2; b[2 * p + 1][1] = r3;
            }
            #pragma unroll
            for (int mt = 0; mt < 2; mt++)
                #pragma unroll
                for (int nt = 0; nt < 4; nt++)
                    mma16816(acc[mt][nt], a[mt], b[nt]);
        }
        __syncthreads();
    }

    #pragma unroll
    for (int mt = 0; mt < 2; mt++) {
        int r0 = bm0 + wm * 32 + mt * 16 + (lane >> 2);
        #pragma unroll
        for (int nt = 0; nt < 4; nt++) {
            int n0 = bn0 + wn * 32 + nt * 8 + 2 * (lane & 3);
            float bb0 = bias[n0], bb1 = bias[n0 + 1];
            if (r0 < M) {
                __nv_bfloat162 pr;
                pr.x = __float2bfloat16(acc[mt][nt][0] + bb0);
                pr.y = __float2bfloat16(acc[mt][nt][1] + bb1);
                *(__nv_bfloat162*)(Out + (size_t)r0 * 256 + n0) = pr;
            }
            if (r0 + 8 < M) {
                __nv_bfloat162 pr;
                pr.x = __float2bfloat16(acc[mt][nt][2] + bb0);
                pr.y = __float2bfloat16(acc[mt][nt][3] + bb1);
                *(__nv_bfloat162*)(Out + (size_t)(r0 + 8) * 256 + n0) = pr;
            }
        }
    }
}

// ---------------- attention: 3-pass (R3-proven), src id direct from g_order ----------------
__global__ void __launch_bounds__(512) k_attn(const float* __restrict__ spd_w_g) {
    int d = blockIdx.x;
    int tid = threadIdx.x, lane = tid & 31, wid = tid >> 5;   // 16 warps
    __shared__ float spdw[40];
    __shared__ float acc_sh[CC];
    __shared__ float maxsh[16 * 8];
    __shared__ float sumh[8];
    __shared__ float maxh[8];
    __shared__ float invh[8];
    if (tid < 40) spdw[tid] = spd_w_g[tid];
    if (tid < CC) acc_sh[tid] = 0.f;
    if (tid < 8)  sumh[tid] = 0.f;

    float qreg[8];
    {
        uint4 qv = ((const uint4*)(g_Qb + d * CC))[lane];
        const __nv_bfloat162* qb = (const __nv_bfloat162*)&qv;
        #pragma unroll
        for (int j = 0; j < 4; j++) {
            float2 f = __bfloat1622float2(qb[j]);
            qreg[2 * j] = f.x; qreg[2 * j + 1] = f.y;
        }
    }
    __syncthreads();

    int base = g_off[d], cnt = g_off[d + 1] - base;
    int head = lane >> 2;
    int wvi = d >> 5; unsigned bt = 1u << (d & 31);

    // pass 1: scores + per-warp max
    float vmax = -1e30f;
    for (int i = wid; i < cnt; i += 16) {
        int s = g_order[base + i];
        uint4 kv = ((const uint4*)(g_Kb + (size_t)s * CC))[lane];
        const __nv_bfloat162* kb = (const __nv_bfloat162*)&kv;
        float p = 0.f;
        #pragma unroll
        for (int j = 0; j < 4; j++) {
            float2 f = __bfloat1622float2(kb[j]);
            p += f.x * qreg[2 * j] + f.y * qreg[2 * j + 1];
        }
        p += __shfl_xor_sync(0xffffffffu, p, 1);
        p += __shfl_xor_sync(0xffffffffu, p, 2);
        int spd = 4;
        if (s < ND) {
            if      (g_F1[s * 8 + wvi] & bt) spd = 1;
            else if (g_F2[s * 8 + wvi] & bt) spd = 2;
            else if (g_F3[s * 8 + wvi] & bt) spd = 3;
        }
        float sc = p * 0.17677669529663687f + spdw[spd * 8 + head];
        vmax = fmaxf(vmax, sc);
        if ((lane & 3) == 0) g_sc[(size_t)(base + i) * 8 + head] = sc;
    }
    if ((lane & 3) == 0) maxsh[wid * 8 + head] = vmax;
    __syncthreads();
    if (tid < 8) {
        float m = -1e30f;
        #pragma unroll
        for (int w = 0; w < 16; w++) m = fmaxf(m, maxsh[w * 8 + tid]);
        maxh[tid] = m;
    }
    __syncthreads();

    // pass 2: exp + per-head sums
    {
        int h = tid & 7;
        float mh = maxh[h];
        float ls = 0.f;
        for (int j = tid; j < cnt * 8; j += 512) {
            size_t idx = (size_t)base * 8 + j;
            float v = __expf(g_sc[idx] - mh);
            g_sc[idx] = v;
            ls += v;
        }
        atomicAdd(&sumh[h], ls);
    }
    __syncthreads();
    if (tid < 8) invh[tid] = (sumh[tid] > 0.f) ? 1.f / sumh[tid] : 0.f;
    __syncthreads();

    // pass 3: weighted V aggregation
    float a8[8];
    #pragma unroll
    for (int j = 0; j < 8; j++) a8[j] = 0.f;
    float inv = invh[head];
    for (int i = wid; i < cnt; i += 16) {
        int s = g_order[base + i];
        float w = g_sc[(size_t)(base + i) * 8 + head] * inv;
        uint4 vv = ((const uint4*)(g_Vb + (size_t)s * CC))[lane];
        const __nv_bfloat162* vb = (const __nv_bfloat162*)&vv;
        #pragma unroll
        for (int j = 0; j < 4; j++) {
            float2 f = __bfloat1622float2(vb[j]);
            a8[2 * j]     += w * f.x;
            a8[2 * j + 1] += w * f.y;
        }
    }
    #pragma unroll
    for (int j = 0; j < 8; j++) atomicAdd(&acc_sh[lane * 8 + j], a8[j]);
    __syncthreads();
    if (tid < CC) g_attn[d * CC + tid] = acc_sh[tid];
}

// ---------------- residual + degree + LayerNorm (two-pass variance) ----------------
__global__ void __launch_bounds__(256) k_ln(const float* __restrict__ x,
                                            const float* __restrict__ gamma,
                                            const float* __restrict__ beta,
                                            float* __restrict__ out, int n) {
    int wid = threadIdx.x >> 5, lane = threadIdx.x & 31;
    int row = blockIdx.x * 8 + wid;
    if (row >= n) return;
    const float4* xp = (const float4*)(x + (size_t)row * CC) + lane * 2;
    float4 v0 = xp[0], v1 = xp[1];
    float h[8] = { v0.x, v0.y, v0.z, v0.w, v1.x, v1.y, v1.z, v1.w };
    float dg = (float)g_deg[row];
    #pragma unroll
    for (int j = 0; j < 8; j++) h[j] += dg;
    if (row < ND) {
        const float4* ap = (const float4*)(g_attn + row * CC) + lane * 2;
        float4 a0 = ap[0], a1 = ap[1];
        h[0] += a0.x; h[1] += a0.y; h[2] += a0.z; h[3] += a0.w;
        h[4] += a1.x; h[5] += a1.y; h[6] += a1.z; h[7] += a1.w;
    }
    float s = 0.f;
    #pragma unroll
    for (int j = 0; j < 8; j++) s += h[j];
    #pragma unroll
    for (int o = 16; o > 0; o >>= 1) s += __shfl_xor_sync(0xffffffffu, s, o);
    float mu = s * (1.f / 256.f);
    float s2 = 0.f;
    #pragma unroll
    for (int j = 0; j < 8; j++) { float dd = h[j] - mu; s2 += dd * dd; }
    #pragma unroll
    for (int o = 16; o > 0; o >>= 1) s2 += __shfl_xor_sync(0xffffffffu, s2, o);
    float var = s2 * (1.f / 256.f);
    float rs = rsqrtf(var + 1e-5f);
    const float4* gp = (const float4*)gamma + lane * 2;
    const float4* bp = (const float4*)beta + lane * 2;
    float4 g0 = gp[0], g1 = gp[1], b0 = bp[0], b1 = bp[1];
    float4 o0, o1;
    o0.x = (h[0] - mu) * rs * g0.x + b0.x;
    o0.y = (h[1] - mu) * rs * g0.y + b0.y;
    o0.z = (h[2] - mu) * rs * g0.z + b0.z;
    o0.w = (h[3] - mu) * rs * g0.w + b0.w;
    o1.x = (h[4] - mu) * rs * g1.x + b1.x;
    o1.y = (h[5] - mu) * rs * g1.y + b1.y;
    o1.z = (h[6] - mu) * rs * g1.z + b1.z;
    o1.w = (h[7] - mu) * rs * g1.w + b1.w;
    float4* op = (float4*)(out + (size_t)row * CC) + lane * 2;
    op[0] = o0; op[1] = o1;
}

// ---------------- launch (GEMMs placed at indices 3,4,5 for ncu window) ----------------
extern "C" void kernel_launch(void* const* d_in, const int* in_sizes, int n_in,
                              void* d_out, int out_size) {
    const float* x     = (const float*)d_in[0];
    const int*   src   = (const int*)d_in[1];
    const int*   dst   = (const int*)d_in[2];
    const float* Wq    = (const float*)d_in[3];
    const float* bq    = (const float*)d_in[4];
    const float* Wk    = (const float*)d_in[5];
    const float* bk    = (const float*)d_in[6];
    const float* Wv    = (const float*)d_in[7];
    const float* bv    = (const float*)d_in[8];
    const float* spd_w = (const float*)d_in[9];
    const float* gamma = (const float*)d_in[10];
    const float* beta  = (const float*)d_in[11];
    float* out = (float*)d_out;

    int n = in_sizes[0] / CC;   // 50000
    int e = in_sizes[1];        // 300000

    dim3 gbig((n + 127) / 128, 4);

    k_init<<<(n + 255) / 256, 256>>>(n);                    // 0
    k_cvt_w<<<(CC * CC + 255) / 256, 256>>>(Wq, Wk, Wv);    // 1
    k_edge<<<256, 256>>>(src, dst, e);                      // 2
    k_gemm<<<gbig, 256>>>(x, 1, bk, n, 0);                  // 3: K
    k_gemm<<<gbig, 256>>>(x, 2, bv, n, 1);                  // 4: V
    k_gemm<<<dim3(2, 4), 256>>>(x, 0, bq, ND, 2);           // 5: Q
    k_bfs_scan<<<1, 256>>>();                               // 6
    k_scatter<<<256, 256>>>(src, dst, e);                   // 7
    k_attn<<<ND, 512>>>(spd_w);                             // 8
    k_ln<<<(n + 7) / 8, 256>>>(x, gamma, beta, out, n);     // 9
}

// round 8
// speedup vs baseline: 1.8728x; 1.8728x over previous
#include <cuda_runtime.h>
#include <cuda_bf16.h>
#include <math.h>

#define NN 50000
#define EE 300000
#define CC 256
#define HH 8
#define ND 256
#define SLCAP 16384

// ---------------- scratch (__device__ globals) ----------------
__device__ __nv_bfloat16 g_xb[NN * CC];
__device__ __nv_bfloat16 g_Kb[NN * CC];
__device__ __nv_bfloat16 g_Vb[NN * CC];
__device__ __nv_bfloat16 g_Qb[ND * CC];
__device__ __nv_bfloat16 g_W[3][CC * CC];   // 0=q, 1=k, 2=v ([1],[2] contiguous -> 512 rows)
__device__ float    g_sc[(size_t)EE * HH];
__device__ float    g_attn[ND * CC];
__device__ int      g_deg[NN];
__device__ int      g_dcnt[ND];
__device__ int      g_off[ND + 1];
__device__ int      g_cur[ND];
__device__ int      g_order[EE];            // SRC node id per sorted slot
__device__ unsigned g_F1[ND * 8], g_F2[ND * 8], g_F3[ND * 8];
__device__ int      g_slist[SLCAP];
__device__ int      g_snum;

// ---------------- init ----------------
__global__ void k_init(int n) {
    int i = blockIdx.x * blockDim.x + threadIdx.x;
    if (i < n)      g_deg[i] = 0;
    if (i < ND)     g_dcnt[i] = 0;
    if (i < ND * 8) g_F1[i] = 0u;
    if (i == 0)     g_snum = 0;
}

// ---------------- converts ----------------
__global__ void k_cvt_x(const float* __restrict__ x, int n4) {
    int i = blockIdx.x * blockDim.x + threadIdx.x;
    if (i >= n4) return;
    float4 v = ((const float4*)x)[i];
    ((__nv_bfloat162*)g_xb)[2 * i]     = __floats2bfloat162_rn(v.x, v.y);
    ((__nv_bfloat162*)g_xb)[2 * i + 1] = __floats2bfloat162_rn(v.z, v.w);
}

__global__ void k_cvt_w(const float* __restrict__ Wq, const float* __restrict__ Wk,
                        const float* __restrict__ Wv) {
    int i = blockIdx.x * blockDim.x + threadIdx.x;
    if (i >= CC * CC) return;
    g_W[0][i] = __float2bfloat16(Wq[i]);
    g_W[1][i] = __float2bfloat16(Wk[i]);
    g_W[2][i] = __float2bfloat16(Wv[i]);
}

// ---------------- edge preprocessing: smem histogram ----------------
__global__ void __launch_bounds__(256) k_edge(const int* __restrict__ src,
                                              const int* __restrict__ dst, int E) {
    __shared__ int sh[ND];
    int t = threadIdx.x;
    sh[t] = 0;
    __syncthreads();
    int stride = gridDim.x * blockDim.x;
    for (int i = blockIdx.x * blockDim.x + t; i < E; i += stride) {
        int s = src[i], d = dst[i];
        atomicAdd(&g_deg[s], 1);
        atomicAdd_block(&sh[d], 1);
        if (s < ND) {
            atomicOr(&g_F1[d * 8 + (s >> 5)], 1u << (s & 31));
            int p = atomicAdd(&g_snum, 1);
            if (p < SLCAP) g_slist[p] = (s << 8) | d;
        }
    }
    __syncthreads();
    int c = sh[t];
    if (c) atomicAdd(&g_dcnt[t], c);
}

// ---------------- BFS: edge-parallel smem atomics (R2 version, 16.5us measured) ----------------
__global__ void k_bfs() {
    __shared__ unsigned sF1[ND * 8], sF2[ND * 8], sF3[ND * 8];
    int t = threadIdx.x;
    for (int i = t; i < ND * 8; i += 256) { sF1[i] = g_F1[i]; sF2[i] = 0u; sF3[i] = 0u; }
    __syncthreads();
    int n = g_snum; if (n > SLCAP) n = SLCAP;
    for (int i = t; i < n; i += 256) {
        int pk = g_slist[i]; int s = pk >> 8, d = pk & 255;
        #pragma unroll
        for (int w = 0; w < 8; w++) {
            unsigned v = sF1[s * 8 + w];
            if (v) atomicOr(&sF2[d * 8 + w], v);
        }
    }
    __syncthreads();
    for (int i = t; i < n; i += 256) {
        int pk = g_slist[i]; int s = pk >> 8, d = pk & 255;
        #pragma unroll
        for (int w = 0; w < 8; w++) {
            unsigned v = sF2[s * 8 + w];
            if (v) atomicOr(&sF3[d * 8 + w], v);
        }
    }
    __syncthreads();
    for (int i = t; i < ND * 8; i += 256) { g_F2[i] = sF2[i]; g_F3[i] = sF3[i]; }
}

// ---------------- scan (256 bins) + degree fold ----------------
__global__ void k_scan() {
    __shared__ int s[ND];
    int t = threadIdx.x;
    int my = g_dcnt[t];
    g_deg[t] += my;
    s[t] = my; __syncthreads();
    for (int o = 1; o < ND; o <<= 1) {
        int v = (t >= o) ? s[t - o] : 0;
        __syncthreads();
        s[t] += v;
        __syncthreads();
    }
    int ex = s[t] - my;
    g_off[t] = ex;
    g_cur[t] = ex;
    if (t == ND - 1) g_off[ND] = s[t];
}

// ---------------- scatter: two-phase, stores SRC id ----------------
__global__ void __launch_bounds__(256) k_scatter(const int* __restrict__ src,
                                                 const int* __restrict__ dst, int E) {
    __shared__ int sh_cnt[ND];
    __shared__ int sh_base[ND];
    __shared__ int sh_cur[ND];
    int t = threadIdx.x;
    int chunk = (E + gridDim.x - 1) / gridDim.x;
    int lo = blockIdx.x * chunk;
    int hi = lo + chunk; if (hi > E) hi = E;
    sh_cnt[t] = 0; sh_cur[t] = 0;
    __syncthreads();
    for (int i = lo + t; i < hi; i += 256)
        atomicAdd_block(&sh_cnt[dst[i]], 1);
    __syncthreads();
    int c = sh_cnt[t];
    sh_base[t] = c ? atomicAdd(&g_cur[t], c) : 0;
    __syncthreads();
    for (int i = lo + t; i < hi; i += 256) {
        int d = dst[i];
        int p = sh_base[d] + atomicAdd_block(&sh_cur[d], 1);
        g_order[p] = src[i];
    }
}

// ======== fused GEMM: A-tile resident, N-blocks of 128, B double-buffered ========
// Out[m, n] = sum_k A[m,k] W[n,k] + bias[n].  A = g_xb bf16 [M,256], W = g_W[wsel].
// nbCnt n-blocks of 128 rows of W.  qmode=1 -> g_Qb; else nb 0,1 -> g_Kb, nb 2,3 -> g_Vb.
__device__ __forceinline__ void mma16816(float* c, const unsigned* a, const unsigned* b) {
    asm volatile(
        "mma.sync.aligned.m16n8k16.row.col.f32.bf16.bf16.f32 "
        "{%0,%1,%2,%3},{%4,%5,%6,%7},{%8,%9},{%0,%1,%2,%3};\n"
        : "+f"(c[0]), "+f"(c[1]), "+f"(c[2]), "+f"(c[3])
        : "r"(a[0]), "r"(a[1]), "r"(a[2]), "r"(a[3]), "r"(b[0]), "r"(b[1]));
}
__device__ __forceinline__ void cp16(unsigned saddr, const void* gptr) {
    asm volatile("cp.async.cg.shared.global [%0], [%1], 16;\n" :: "r"(saddr), "l"(gptr));
}

#define LDT 264                       // halves per smem row (528 B, conflict-free)
#define TILE_B (128 * 528)            // 67584 bytes per 128x256 bf16 tile
#define GEMM_SMEM (3 * TILE_B)        // A + 2 B buffers = 202752 B

__global__ void __launch_bounds__(256) k_gemm_fused(int wsel, int nbCnt, int M, int qmode,
                                                    const float* __restrict__ bias0,
                                                    const float* __restrict__ bias1) {
    extern __shared__ char smem[];
    const __nv_bfloat16* W = g_W[wsel];
    unsigned sbase = (unsigned)__cvta_generic_to_shared(smem);
    unsigned sA = sbase;
    unsigned sB[2] = { sbase + TILE_B, sbase + 2 * TILE_B };

    int tid = threadIdx.x, lane = tid & 31, wid = tid >> 5;
    int wm = wid & 3, wn = wid >> 2;              // 4 x 2 warps; warp tile 32 x 64
    int bm0 = blockIdx.x * 128;

    // ---- A tile: 128 rows x 32 chunks of 16B; 16 chunks per thread ----
    #pragma unroll
    for (int i = 0; i < 16; i++) {
        int c = tid + i * 256;
        int row = c >> 5, jc = c & 31;
        int rg = bm0 + row; if (rg >= M) rg = M - 1;
        cp16(sA + (unsigned)(row * 528 + jc * 16), g_xb + (size_t)rg * 256 + jc * 8);
    }
    // ---- B block 0 ----
    {
        const __nv_bfloat16* Wc = W;
        #pragma unroll
        for (int i = 0; i < 16; i++) {
            int c = tid + i * 256;
            int row = c >> 5, jc = c & 31;
            cp16(sB[0] + (unsigned)(row * 528 + jc * 16), Wc + (size_t)row * 256 + jc * 8);
        }
    }
    asm volatile("cp.async.commit_group;\n" ::);
    if (nbCnt > 1) {
        const __nv_bfloat16* Wc = W + (size_t)128 * 256;
        #pragma unroll
        for (int i = 0; i < 16; i++) {
            int c = tid + i * 256;
            int row = c >> 5, jc = c & 31;
            cp16(sB[1] + (unsigned)(row * 528 + jc * 16), Wc + (size_t)row * 256 + jc * 8);
        }
        asm volatile("cp.async.commit_group;\n" ::);
    }

    for (int nb = 0; nb < nbCnt; nb++) {
        if (nb < nbCnt - 1) asm volatile("cp.async.wait_group 1;\n" ::);
        else                asm volatile("cp.async.wait_group 0;\n" ::);
        __syncthreads();

        float acc[2][8][4];
        #pragma unroll
        for (int i = 0; i < 2; i++)
            #pragma unroll
            for (int j = 0; j < 8; j++)
                #pragma unroll
                for (int k = 0; k < 4; k++) acc[i][j][k] = 0.f;

        unsigned Bb = sB[nb & 1];
        #pragma unroll
        for (int kk = 0; kk < 256; kk += 16) {
            unsigned a[2][4], b[8][2];
            #pragma unroll
            for (int mt = 0; mt < 2; mt++) {
                int r = wm * 32 + mt * 16 + (lane & 15);
                int c = kk + (lane >> 4) * 8;
                unsigned addr = sA + (unsigned)(r * LDT + c) * 2;
                asm volatile("ldmatrix.sync.aligned.m8n8.x4.shared.b16 {%0,%1,%2,%3},[%4];"
                    : "=r"(a[mt][0]), "=r"(a[mt][1]), "=r"(a[mt][2]), "=r"(a[mt][3])
                    : "r"(addr));
            }
            #pragma unroll
            for (int p = 0; p < 4; p++) {
                int r = wn * 64 + (2 * p + (lane >> 4)) * 8 + (lane & 7);
                int c = kk + ((lane >> 3) & 1) * 8;
                unsigned addr = Bb + (unsigned)(r * LDT + c) * 2;
                unsigned r0, r1, r2, r3;
                asm volatile("ldmatrix.sync.aligned.m8n8.x4.shared.b16 {%0,%1,%2,%3},[%4];"
                    : "=r"(r0), "=r"(r1), "=r"(r2), "=r"(r3) : "r"(addr));
                b[2 * p][0] = r0; b[2 * p][1] = r1;
                b[2 * p + 1][0] = r2; b[2 * p + 1][1] = r3;
            }
            #pragma unroll
            for (int mt = 0; mt < 2; mt++)
                #pragma unroll
                for (int nt = 0; nt < 8; nt++)
                    mma16816(acc[mt][nt], a[mt], b[nt]);
        }
        __syncthreads();

        if (nb + 2 < nbCnt) {
            const __nv_bfloat16* Wc = W + (size_t)(nb + 2) * 128 * 256;
            unsigned dstb = sB[nb & 1];
            #pragma unroll
            for (int i = 0; i < 16; i++) {
                int c = tid + i * 256;
                int row = c >> 5, jc = c & 31;
                cp16(dstb + (unsigned)(row * 528 + jc * 16), Wc + (size_t)row * 256 + jc * 8);
            }
            asm volatile("cp.async.commit_group;\n" ::);
        }

        // epilogue for this n-block
        int gcb = nb * 128 + wn * 64;
        const float* bias; __nv_bfloat16* Out; int col0;
        if (qmode)          { Out = g_Qb; bias = bias0; col0 = gcb; }
        else if (gcb < 256) { Out = g_Kb; bias = bias0; col0 = gcb; }
        else                { Out = g_Vb; bias = bias1; col0 = gcb - 256; }
        #pragma unroll
        for (int mt = 0; mt < 2; mt++) {
            int r0 = bm0 + wm * 32 + mt * 16 + (lane >> 2);
            #pragma unroll
            for (int nt = 0; nt < 8; nt++) {
                int n0 = col0 + nt * 8 + 2 * (lane & 3);
                float bb0 = bias[n0], bb1 = bias[n0 + 1];
                if (r0 < M) {
                    __nv_bfloat162 pr = __floats2bfloat162_rn(acc[mt][nt][0] + bb0,
                                                              acc[mt][nt][1] + bb1);
                    *(__nv_bfloat162*)(Out + (size_t)r0 * 256 + n0) = pr;
                }
                if (r0 + 8 < M) {
                    __nv_bfloat162 pr = __floats2bfloat162_rn(acc[mt][nt][2] + bb0,
                                                              acc[mt][nt][3] + bb1);
                    *(__nv_bfloat162*)(Out + (size_t)(r0 + 8) * 256 + n0) = pr;
                }
            }
        }
    }
}

// ---------------- attention: 3-pass, src id direct from g_order ----------------
__global__ void __launch_bounds__(512) k_attn(const float* __restrict__ spd_w_g) {
    int d = blockIdx.x;
    int tid = threadIdx.x, lane = tid & 31, wid = tid >> 5;
    __shared__ float spdw[40];
    __shared__ float acc_sh[CC];
    __shared__ float maxsh[16 * 8];
    __shared__ float sumh[8];
    __shared__ float maxh[8];
    __shared__ float invh[8];
    if (tid < 40) spdw[tid] = spd_w_g[tid];
    if (tid < CC) acc_sh[tid] = 0.f;
    if (tid < 8)  sumh[tid] = 0.f;

    float qreg[8];
    {
        uint4 qv = ((const uint4*)(g_Qb + d * CC))[lane];
        const __nv_bfloat162* qb = (const __nv_bfloat162*)&qv;
        #pragma unroll
        for (int j = 0; j < 4; j++) {
            float2 f = __bfloat1622float2(qb[j]);
            qreg[2 * j] = f.x; qreg[2 * j + 1] = f.y;
        }
    }
    __syncthreads();

    int base = g_off[d], cnt = g_off[d + 1] - base;
    int head = lane >> 2;
    int wvi = d >> 5; unsigned bt = 1u << (d & 31);

    float vmax = -1e30f;
    for (int i = wid; i < cnt; i += 16) {
        int s = g_order[base + i];
        uint4 kv = ((const uint4*)(g_Kb + (size_t)s * CC))[lane];
        const __nv_bfloat162* kb = (const __nv_bfloat162*)&kv;
        float p = 0.f;
        #pragma unroll
        for (int j = 0; j < 4; j++) {
            float2 f = __bfloat1622float2(kb[j]);
            p += f.x * qreg[2 * j] + f.y * qreg[2 * j + 1];
        }
        p += __shfl_xor_sync(0xffffffffu, p, 1);
        p += __shfl_xor_sync(0xffffffffu, p, 2);
        int spd = 4;
        if (s < ND) {
            if      (g_F1[s * 8 + wvi] & bt) spd = 1;
            else if (g_F2[s * 8 + wvi] & bt) spd = 2;
            else if (g_F3[s * 8 + wvi] & bt) spd = 3;
        }
        float sc = p * 0.17677669529663687f + spdw[spd * 8 + head];
        vmax = fmaxf(vmax, sc);
        if ((lane & 3) == 0) g_sc[(size_t)(base + i) * 8 + head] = sc;
    }
    if ((lane & 3) == 0) maxsh[wid * 8 + head] = vmax;
    __syncthreads();
    if (tid < 8) {
        float m = -1e30f;
        #pragma unroll
        for (int w = 0; w < 16; w++) m = fmaxf(m, maxsh[w * 8 + tid]);
        maxh[tid] = m;
    }
    __syncthreads();

    {
        int h = tid & 7;
        float mh = maxh[h];
        float ls = 0.f;
        for (int j = tid; j < cnt * 8; j += 512) {
            size_t idx = (size_t)base * 8 + j;
            float v = __expf(g_sc[idx] - mh);
            g_sc[idx] = v;
            ls += v;
        }
        atomicAdd(&sumh[h], ls);
    }
    __syncthreads();
    if (tid < 8) invh[tid] = (sumh[tid] > 0.f) ? 1.f / sumh[tid] : 0.f;
    __syncthreads();

    float a8[8];
    #pragma unroll
    for (int j = 0; j < 8; j++) a8[j] = 0.f;
    float inv = invh[head];
    for (int i = wid; i < cnt; i += 16) {
        int s = g_order[base + i];
        float w = g_sc[(size_t)(base + i) * 8 + head] * inv;
        uint4 vv = ((const uint4*)(g_Vb + (size_t)s * CC))[lane];
        const __nv_bfloat162* vb = (const __nv_bfloat162*)&vv;
        #pragma unroll
        for (int j = 0; j < 4; j++) {
            float2 f = __bfloat1622float2(vb[j]);
            a8[2 * j]     += w * f.x;
            a8[2 * j + 1] += w * f.y;
        }
    }
    #pragma unroll
    for (int j = 0; j < 8; j++) atomicAdd(&acc_sh[lane * 8 + j], a8[j]);
    __syncthreads();
    if (tid < CC) g_attn[d * CC + tid] = acc_sh[tid];
}

// ---------------- residual + degree + LayerNorm (two-pass variance) ----------------
__global__ void __launch_bounds__(256) k_ln(const float* __restrict__ x,
                                            const float* __restrict__ gamma,
                                            const float* __restrict__ beta,
                                            float* __restrict__ out, int n) {
    int wid = threadIdx.x >> 5, lane = threadIdx.x & 31;
    int row = blockIdx.x * 8 + wid;
    if (row >= n) return;
    const float4* xp = (const float4*)(x + (size_t)row * CC) + lane * 2;
    float4 v0 = xp[0], v1 = xp[1];
    float h[8] = { v0.x, v0.y, v0.z, v0.w, v1.x, v1.y, v1.z, v1.w };
    float dg = (float)g_deg[row];
    #pragma unroll
    for (int j = 0; j < 8; j++) h[j] += dg;
    if (row < ND) {
        const float4* ap = (const float4*)(g_attn + row * CC) + lane * 2;
        float4 a0 = ap[0], a1 = ap[1];
        h[0] += a0.x; h[1] += a0.y; h[2] += a0.z; h[3] += a0.w;
        h[4] += a1.x; h[5] += a1.y; h[6] += a1.z; h[7] += a1.w;
    }
    float s = 0.f;
    #pragma unroll
    for (int j = 0; j < 8; j++) s += h[j];
    #pragma unroll
    for (int o = 16; o > 0; o >>= 1) s += __shfl_xor_sync(0xffffffffu, s, o);
    float mu = s * (1.f / 256.f);
    float s2 = 0.f;
    #pragma unroll
    for (int j = 0; j < 8; j++) { float dd = h[j] - mu; s2 += dd * dd; }
    #pragma unroll
    for (int o = 16; o > 0; o >>= 1) s2 += __shfl_xor_sync(0xffffffffu, s2, o);
    float var = s2 * (1.f / 256.f);
    float rs = rsqrtf(var + 1e-5f);
    const float4* gp = (const float4*)gamma + lane * 2;
    const float4* bp = (const float4*)beta + lane * 2;
    float4 g0 = gp[0], g1 = gp[1], b0 = bp[0], b1 = bp[1];
    float4 o0, o1;
    o0.x = (h[0] - mu) * rs * g0.x + b0.x;
    o0.y = (h[1] - mu) * rs * g0.y + b0.y;
    o0.z = (h[2] - mu) * rs * g0.z + b0.z;
    o0.w = (h[3] - mu) * rs * g0.w + b0.w;
    o1.x = (h[4] - mu) * rs * g1.x + b1.x;
    o1.y = (h[5] - mu) * rs * g1.y + b1.y;
    o1.z = (h[6] - mu) * rs * g1.z + b1.z;
    o1.w = (h[7] - mu) * rs * g1.w + b1.w;
    float4* op = (float4*)(out + (size_t)row * CC) + lane * 2;
    op[0] = o0; op[1] = o1;
}

// ---------------- launch (fused GEMM at ncu-captured index 3) ----------------
extern "C" void kernel_launch(void* const* d_in, const int* in_sizes, int n_in,
                              void* d_out, int out_size) {
    const float* x     = (const float*)d_in[0];
    const int*   src   = (const int*)d_in[1];
    const int*   dst   = (const int*)d_in[2];
    const float* Wq    = (const float*)d_in[3];
    const float* bq    = (const float*)d_in[4];
    const float* Wk    = (const float*)d_in[5];
    const float* bk    = (const float*)d_in[6];
    const float* Wv    = (const float*)d_in[7];
    const float* bv    = (const float*)d_in[8];
    const float* spd_w = (const float*)d_in[9];
    const float* gamma = (const float*)d_in[10];
    const float* beta  = (const float*)d_in[11];
    float* out = (float*)d_out;

    int n = in_sizes[0] / CC;   // 50000
    int e = in_sizes[1];        // 300000

    cudaFuncSetAttribute(k_gemm_fused, cudaFuncAttributeMaxDynamicSharedMemorySize, GEMM_SMEM);

    k_cvt_w<<<(CC * CC + 255) / 256, 256>>>(Wq, Wk, Wv);                    // 0
    k_cvt_x<<<(n * CC / 4 + 255) / 256, 256>>>(x, n * CC / 4);              // 1
    k_init<<<(n + 255) / 256, 256>>>(n);                                    // 2
    k_gemm_fused<<<(n + 127) / 128, 256, GEMM_SMEM>>>(1, 4, n, 0, bk, bv);  // 3: K|V
    k_gemm_fused<<<2, 256, GEMM_SMEM>>>(0, 2, ND, 1, bq, bq);               // 4: Q
    k_edge<<<256, 256>>>(src, dst, e);                                      // 5
    k_bfs<<<1, 256>>>();                                                    // 6
    k_scan<<<1, 256>>>();                                                   // 7
    k_scatter<<<256, 256>>>(src, dst, e);                                   // 8
    k_attn<<<ND, 512>>>(spd_w);                                             // 9
    k_ln<<<(n + 7) / 8, 256>>>(x, gamma, beta, out, n);                     // 10
}

// round 12
// speedup vs baseline: 2.1873x; 1.1680x over previous
#include <cuda_runtime.h>
#include <cuda_bf16.h>
#include <math.h>

#define NN 50000
#define EE 300000
#define CC 256
#define HH 8
#define ND 256
#define SLCAP 16384

// ---------------- scratch (__device__ globals) ----------------
__device__ __nv_bfloat16 g_xb[NN * CC];
__device__ __nv_bfloat16 g_Kb[NN * CC];
__device__ __nv_bfloat16 g_Vb[NN * CC];
__device__ __nv_bfloat16 g_Qb[ND * CC];
__device__ __nv_bfloat16 g_W[3][CC * CC];   // 0=q, 1=k, 2=v ([1],[2] contiguous -> 512 rows)
__device__ float    g_sc[(size_t)EE * HH];
__device__ float    g_attn[ND * CC];
__device__ int      g_deg[NN];
__device__ int      g_dcnt[ND];
__device__ int      g_off[ND + 1];
__device__ int      g_cur[ND];
__device__ int      g_order[EE];            // SRC node id per sorted slot
__device__ unsigned g_F1[ND * 8], g_F2[ND * 8], g_F3[ND * 8];
__device__ int      g_slist[SLCAP];
__device__ int      g_snum;

// ---------------- init ----------------
__global__ void k_init(int n) {
    int i = blockIdx.x * blockDim.x + threadIdx.x;
    if (i < n)      g_deg[i] = 0;
    if (i < ND)     g_dcnt[i] = 0;
    if (i < ND * 8) g_F1[i] = 0u;
    if (i == 0)     g_snum = 0;
}

// ---------------- converts ----------------
__global__ void k_cvt_x(const float* __restrict__ x, int n4) {
    int i = blockIdx.x * blockDim.x + threadIdx.x;
    if (i >= n4) return;
    float4 v = ((const float4*)x)[i];
    ((__nv_bfloat162*)g_xb)[2 * i]     = __floats2bfloat162_rn(v.x, v.y);
    ((__nv_bfloat162*)g_xb)[2 * i + 1] = __floats2bfloat162_rn(v.z, v.w);
}

__global__ void k_cvt_w(const float* __restrict__ Wq, const float* __restrict__ Wk,
                        const float* __restrict__ Wv) {
    int i = blockIdx.x * blockDim.x + threadIdx.x;
    if (i >= CC * CC) return;
    g_W[0][i] = __float2bfloat16(Wq[i]);
    g_W[1][i] = __float2bfloat16(Wk[i]);
    g_W[2][i] = __float2bfloat16(Wv[i]);
}

// ---------------- edge preprocessing: smem histogram ----------------
__global__ void __launch_bounds__(256) k_edge(const int* __restrict__ src,
                                              const int* __restrict__ dst, int E) {
    __shared__ int sh[ND];
    int t = threadIdx.x;
    sh[t] = 0;
    __syncthreads();
    int stride = gridDim.x * blockDim.x;
    for (int i = blockIdx.x * blockDim.x + t; i < E; i += stride) {
        int s = src[i], d = dst[i];
        atomicAdd(&g_deg[s], 1);
        atomicAdd_block(&sh[d], 1);
        if (s < ND) {
            atomicOr(&g_F1[d * 8 + (s >> 5)], 1u << (s & 31));
            int p = atomicAdd(&g_snum, 1);
            if (p < SLCAP) g_slist[p] = (s << 8) | d;
        }
    }
    __syncthreads();
    int c = sh[t];
    if (c) atomicAdd(&g_dcnt[t], c);
}

// ---------------- BFS: edge-parallel smem atomics ----------------
__global__ void k_bfs() {
    __shared__ unsigned sF1[ND * 8], sF2[ND * 8], sF3[ND * 8];
    int t = threadIdx.x;
    for (int i = t; i < ND * 8; i += 256) { sF1[i] = g_F1[i]; sF2[i] = 0u; sF3[i] = 0u; }
    __syncthreads();
    int n = g_snum; if (n > SLCAP) n = SLCAP;
    for (int i = t; i < n; i += 256) {
        int pk = g_slist[i]; int s = pk >> 8, d = pk & 255;
        #pragma unroll
        for (int w = 0; w < 8; w++) {
            unsigned v = sF1[s * 8 + w];
            if (v) atomicOr(&sF2[d * 8 + w], v);
        }
    }
    __syncthreads();
    for (int i = t; i < n; i += 256) {
        int pk = g_slist[i]; int s = pk >> 8, d = pk & 255;
        #pragma unroll
        for (int w = 0; w < 8; w++) {
            unsigned v = sF2[s * 8 + w];
            if (v) atomicOr(&sF3[d * 8 + w], v);
        }
    }
    __syncthreads();
    for (int i = t; i < ND * 8; i += 256) { g_F2[i] = sF2[i]; g_F3[i] = sF3[i]; }
}

// ---------------- scan (256 bins) + degree fold ----------------
__global__ void k_scan() {
    __shared__ int s[ND];
    int t = threadIdx.x;
    int my = g_dcnt[t];
    g_deg[t] += my;
    s[t] = my; __syncthreads();
    for (int o = 1; o < ND; o <<= 1) {
        int v = (t >= o) ? s[t - o] : 0;
        __syncthreads();
        s[t] += v;
        __syncthreads();
    }
    int ex = s[t] - my;
    g_off[t] = ex;
    g_cur[t] = ex;
    if (t == ND - 1) g_off[ND] = s[t];
}

// ---------------- scatter: two-phase, stores SRC id ----------------
__global__ void __launch_bounds__(256) k_scatter(const int* __restrict__ src,
                                                 const int* __restrict__ dst, int E) {
    __shared__ int sh_cnt[ND];
    __shared__ int sh_base[ND];
    __shared__ int sh_cur[ND];
    int t = threadIdx.x;
    int chunk = (E + gridDim.x - 1) / gridDim.x;
    int lo = blockIdx.x * chunk;
    int hi = lo + chunk; if (hi > E) hi = E;
    sh_cnt[t] = 0; sh_cur[t] = 0;
    __syncthreads();
    for (int i = lo + t; i < hi; i += 256)
        atomicAdd_block(&sh_cnt[dst[i]], 1);
    __syncthreads();
    int c = sh_cnt[t];
    sh_base[t] = c ? atomicAdd(&g_cur[t], c) : 0;
    __syncthreads();
    for (int i = lo + t; i < hi; i += 256) {
        int d = dst[i];
        int p = sh_base[d] + atomicAdd_block(&sh_cur[d], 1);
        g_order[p] = src[i];
    }
}

// ======== fused GEMM: A-tile resident, N-blocks of 128, B double-buffered ========
__device__ __forceinline__ void mma16816(float* c, const unsigned* a, const unsigned* b) {
    asm volatile(
        "mma.sync.aligned.m16n8k16.row.col.f32.bf16.bf16.f32 "
        "{%0,%1,%2,%3},{%4,%5,%6,%7},{%8,%9},{%0,%1,%2,%3};\n"
        : "+f"(c[0]), "+f"(c[1]), "+f"(c[2]), "+f"(c[3])
        : "r"(a[0]), "r"(a[1]), "r"(a[2]), "r"(a[3]), "r"(b[0]), "r"(b[1]));
}
__device__ __forceinline__ void cp16(unsigned saddr, const void* gptr) {
    asm volatile("cp.async.cg.shared.global [%0], [%1], 16;\n" :: "r"(saddr), "l"(gptr));
}

#define LDT 264                       // halves per smem row (528 B)
#define TILE_B (128 * 528)
#define GEMM_SMEM (3 * TILE_B)        // 202752 B

__global__ void __launch_bounds__(256) k_gemm_fused(int wsel, int nbCnt, int M, int qmode,
                                                    const float* __restrict__ bias0,
                                                    const float* __restrict__ bias1) {
    extern __shared__ char smem[];
    const __nv_bfloat16* W = g_W[wsel];
    unsigned sbase = (unsigned)__cvta_generic_to_shared(smem);
    unsigned sA = sbase;
    unsigned sB[2] = { sbase + TILE_B, sbase + 2 * TILE_B };

    int tid = threadIdx.x, lane = tid & 31, wid = tid >> 5;
    int wm = wid & 3, wn = wid >> 2;              // 4 x 2 warps; warp tile 32 x 64
    int bm0 = blockIdx.x * 128;

    #pragma unroll
    for (int i = 0; i < 16; i++) {
        int c = tid + i * 256;
        int row = c >> 5, jc = c & 31;
        int rg = bm0 + row; if (rg >= M) rg = M - 1;
        cp16(sA + (unsigned)(row * 528 + jc * 16), g_xb + (size_t)rg * 256 + jc * 8);
    }
    {
        const __nv_bfloat16* Wc = W;
        #pragma unroll
        for (int i = 0; i < 16; i++) {
            int c = tid + i * 256;
            int row = c >> 5, jc = c & 31;
            cp16(sB[0] + (unsigned)(row * 528 + jc * 16), Wc + (size_t)row * 256 + jc * 8);
        }
    }
    asm volatile("cp.async.commit_group;\n" ::);
    if (nbCnt > 1) {
        const __nv_bfloat16* Wc = W + (size_t)128 * 256;
        #pragma unroll
        for (int i = 0; i < 16; i++) {
            int c = tid + i * 256;
            int row = c >> 5, jc = c & 31;
            cp16(sB[1] + (unsigned)(row * 528 + jc * 16), Wc + (size_t)row * 256 + jc * 8);
        }
        asm volatile("cp.async.commit_group;\n" ::);
    }

    for (int nb = 0; nb < nbCnt; nb++) {
        if (nb < nbCnt - 1) asm volatile("cp.async.wait_group 1;\n" ::);
        else                asm volatile("cp.async.wait_group 0;\n" ::);
        __syncthreads();

        float acc[2][8][4];
        #pragma unroll
        for (int i = 0; i < 2; i++)
            #pragma unroll
            for (int j = 0; j < 8; j++)
                #pragma unroll
                for (int k = 0; k < 4; k++) acc[i][j][k] = 0.f;

        unsigned Bb = sB[nb & 1];
        #pragma unroll
        for (int kk = 0; kk < 256; kk += 16) {
            unsigned a[2][4], b[8][2];
            #pragma unroll
            for (int mt = 0; mt < 2; mt++) {
                int r = wm * 32 + mt * 16 + (lane & 15);
                int c = kk + (lane >> 4) * 8;
                unsigned addr = sA + (unsigned)(r * LDT + c) * 2;
                asm volatile("ldmatrix.sync.aligned.m8n8.x4.shared.b16 {%0,%1,%2,%3},[%4];"
                    : "=r"(a[mt][0]), "=r"(a[mt][1]), "=r"(a[mt][2]), "=r"(a[mt][3])
                    : "r"(addr));
            }
            #pragma unroll
            for (int p = 0; p < 4; p++) {
                int r = wn * 64 + (2 * p + (lane >> 4)) * 8 + (lane & 7);
                int c = kk + ((lane >> 3) & 1) * 8;
                unsigned addr = Bb + (unsigned)(r * LDT + c) * 2;
                unsigned r0, r1, r2, r3;
                asm volatile("ldmatrix.sync.aligned.m8n8.x4.shared.b16 {%0,%1,%2,%3},[%4];"
                    : "=r"(r0), "=r"(r1), "=r"(r2), "=r"(r3) : "r"(addr));
                b[2 * p][0] = r0; b[2 * p][1] = r1;
                b[2 * p + 1][0] = r2; b[2 * p + 1][1] = r3;
            }
            #pragma unroll
            for (int mt = 0; mt < 2; mt++)
                #pragma unroll
                for (int nt = 0; nt < 8; nt++)
                    mma16816(acc[mt][nt], a[mt], b[nt]);
        }
        __syncthreads();

        if (nb + 2 < nbCnt) {
            const __nv_bfloat16* Wc = W + (size_t)(nb + 2) * 128 * 256;
            unsigned dstb = sB[nb & 1];
            #pragma unroll
            for (int i = 0; i < 16; i++) {
                int c = tid + i * 256;
                int row = c >> 5, jc = c & 31;
                cp16(dstb + (unsigned)(row * 528 + jc * 16), Wc + (size_t)row * 256 + jc * 8);
            }
            asm volatile("cp.async.commit_group;\n" ::);
        }

        int gcb = nb * 128 + wn * 64;
        const float* bias; __nv_bfloat16* Out; int col0;
        if (qmode)          { Out = g_Qb; bias = bias0; col0 = gcb; }
        else if (gcb < 256) { Out = g_Kb; bias = bias0; col0 = gcb; }
        else                { Out = g_Vb; bias = bias1; col0 = gcb - 256; }
        #pragma unroll
        for (int mt = 0; mt < 2; mt++) {
            int r0 = bm0 + wm * 32 + mt * 16 + (lane >> 2);
            #pragma unroll
            for (int nt = 0; nt < 8; nt++) {
                int n0 = col0 + nt * 8 + 2 * (lane & 3);
                float bb0 = bias[n0], bb1 = bias[n0 + 1];
                if (r0 < M) {
                    __nv_bfloat162 pr = __floats2bfloat162_rn(acc[mt][nt][0] + bb0,
                                                              acc[mt][nt][1] + bb1);
                    *(__nv_bfloat162*)(Out + (size_t)r0 * 256 + n0) = pr;
                }
                if (r0 + 8 < M) {
                    __nv_bfloat162 pr = __floats2bfloat162_rn(acc[mt][nt][2] + bb0,
                                                              acc[mt][nt][3] + bb1);
                    *(__nv_bfloat162*)(Out + (size_t)(r0 + 8) * 256 + n0) = pr;
                }
            }
        }
    }
}

// ---------------- attention: 3-pass ----------------
__global__ void __launch_bounds__(512) k_attn(const float* __restrict__ spd_w_g) {
    int d = blockIdx.x;
    int tid = threadIdx.x, lane = tid & 31, wid = tid >> 5;
    __shared__ float spdw[40];
    __shared__ float acc_sh[CC];
    __shared__ float maxsh[16 * 8];
    __shared__ float sumh[8];
    __shared__ float maxh[8];
    __shared__ float invh[8];
    if (tid < 40) spdw[tid] = spd_w_g[tid];
    if (tid < CC) acc_sh[tid] = 0.f;
    if (tid < 8)  sumh[tid] = 0.f;

    float qreg[8];
    {
        uint4 qv = ((const uint4*)(g_Qb + d * CC))[lane];
        const __nv_bfloat162* qb = (const __nv_bfloat162*)&qv;
        #pragma unroll
        for (int j = 0; j < 4; j++) {
            float2 f = __bfloat1622float2(qb[j]);
            qreg[2 * j] = f.x; qreg[2 * j + 1] = f.y;
        }
    }
    __syncthreads();

    int base = g_off[d], cnt = g_off[d + 1] - base;
    int head = lane >> 2;
    int wvi = d >> 5; unsigned bt = 1u << (d & 31);

    float vmax = -1e30f;
    for (int i = wid; i < cnt; i += 16) {
        int s = g_order[base + i];
        uint4 kv = ((const uint4*)(g_Kb + (size_t)s * CC))[lane];
        const __nv_bfloat162* kb = (const __nv_bfloat162*)&kv;
        float p = 0.f;
        #pragma unroll
        for (int j = 0; j < 4; j++) {
            float2 f = __bfloat1622float2(kb[j]);
            p += f.x * qreg[2 * j] + f.y * qreg[2 * j + 1];
        }
        p += __shfl_xor_sync(0xffffffffu, p, 1);
        p += __shfl_xor_sync(0xffffffffu, p, 2);
        int spd = 4;
        if (s < ND) {
            if      (g_F1[s * 8 + wvi] & bt) spd = 1;
            else if (g_F2[s * 8 + wvi] & bt) spd = 2;
            else if (g_F3[s * 8 + wvi] & bt) spd = 3;
        }
        float sc = p * 0.17677669529663687f + spdw[spd * 8 + head];
        vmax = fmaxf(vmax, sc);
        if ((lane & 3) == 0) g_sc[(size_t)(base + i) * 8 + head] = sc;
    }
    if ((lane & 3) == 0) maxsh[wid * 8 + head] = vmax;
    __syncthreads();
    if (tid < 8) {
        float m = -1e30f;
        #pragma unroll
        for (int w = 0; w < 16; w++) m = fmaxf(m, maxsh[w * 8 + tid]);
        maxh[tid] = m;
    }
    __syncthreads();

    {
        int h = tid & 7;
        float mh = maxh[h];
        float ls = 0.f;
        for (int j = tid; j < cnt * 8; j += 512) {
            size_t idx = (size_t)base * 8 + j;
            float v = __expf(g_sc[idx] - mh);
            g_sc[idx] = v;
            ls += v;
        }
        atomicAdd(&sumh[h], ls);
    }
    __syncthreads();
    if (tid < 8) invh[tid] = (sumh[tid] > 0.f) ? 1.f / sumh[tid] : 0.f;
    __syncthreads();

    float a8[8];
    #pragma unroll
    for (int j = 0; j < 8; j++) a8[j] = 0.f;
    float inv = invh[head];
    for (int i = wid; i < cnt; i += 16) {
        int s = g_order[base + i];
        float w = g_sc[(size_t)(base + i) * 8 + head] * inv;
        uint4 vv = ((const uint4*)(g_Vb + (size_t)s * CC))[lane];
        const __nv_bfloat162* vb = (const __nv_bfloat162*)&vv;
        #pragma unroll
        for (int j = 0; j < 4; j++) {
            float2 f = __bfloat1622float2(vb[j]);
            a8[2 * j]     += w * f.x;
            a8[2 * j + 1] += w * f.y;
        }
    }
    #pragma unroll
    for (int j = 0; j < 8; j++) atomicAdd(&acc_sh[lane * 8 + j], a8[j]);
    __syncthreads();
    if (tid < CC) g_attn[d * CC + tid] = acc_sh[tid];
}

// ---------------- residual + degree + LayerNorm ----------------
__global__ void __launch_bounds__(256) k_ln(const float* __restrict__ x,
                                            const float* __restrict__ gamma,
                                            const float* __restrict__ beta,
                                            float* __restrict__ out, int n) {
    int wid = threadIdx.x >> 5, lane = threadIdx.x & 31;
    int row = blockIdx.x * 8 + wid;
    if (row >= n) return;
    const float4* xp = (const float4*)(x + (size_t)row * CC) + lane * 2;
    float4 v0 = xp[0], v1 = xp[1];
    float h[8] = { v0.x, v0.y, v0.z, v0.w, v1.x, v1.y, v1.z, v1.w };
    float dg = (float)g_deg[row];
    #pragma unroll
    for (int j = 0; j < 8; j++) h[j] += dg;
    if (row < ND) {
        const float4* ap = (const float4*)(g_attn + row * CC) + lane * 2;
        float4 a0 = ap[0], a1 = ap[1];
        h[0] += a0.x; h[1] += a0.y; h[2] += a0.z; h[3] += a0.w;
        h[4] += a1.x; h[5] += a1.y; h[6] += a1.z; h[7] += a1.w;
    }
    float s = 0.f;
    #pragma unroll
    for (int j = 0; j < 8; j++) s += h[j];
    #pragma unroll
    for (int o = 16; o > 0; o >>= 1) s += __shfl_xor_sync(0xffffffffu, s, o);
    float mu = s * (1.f / 256.f);
    float s2 = 0.f;
    #pragma unroll
    for (int j = 0; j < 8; j++) { float dd = h[j] - mu; s2 += dd * dd; }
    #pragma unroll
    for (int o = 16; o > 0; o >>= 1) s2 += __shfl_xor_sync(0xffffffffu, s2, o);
    float var = s2 * (1.f / 256.f);
    float rs = rsqrtf(var + 1e-5f);
    const float4* gp = (const float4*)gamma + lane * 2;
    const float4* bp = (const float4*)beta + lane * 2;
    float4 g0 = gp[0], g1 = gp[1], b0 = bp[0], b1 = bp[1];
    float4 o0, o1;
    o0.x = (h[0] - mu) * rs * g0.x + b0.x;
    o0.y = (h[1] - mu) * rs * g0.y + b0.y;
    o0.z = (h[2] - mu) * rs * g0.z + b0.z;
    o0.w = (h[3] - mu) * rs * g0.w + b0.w;
    o1.x = (h[4] - mu) * rs * g1.x + b1.x;
    o1.y = (h[5] - mu) * rs * g1.y + b1.y;
    o1.z = (h[6] - mu) * rs * g1.z + b1.z;
    o1.w = (h[7] - mu) * rs * g1.w + b1.w;
    float4* op = (float4*)(out + (size_t)row * CC) + lane * 2;
    op[0] = o0; op[1] = o1;
}

// ---------------- launch: edge chain on a side stream, overlapped with GEMM chain ----------------
extern "C" void kernel_launch(void* const* d_in, const int* in_sizes, int n_in,
                              void* d_out, int out_size) {
    const float* x     = (const float*)d_in[0];
    const int*   src   = (const int*)d_in[1];
    const int*   dst   = (const int*)d_in[2];
    const float* Wq    = (const float*)d_in[3];
    const float* bq    = (const float*)d_in[4];
    const float* Wk    = (const float*)d_in[5];
    const float* bk    = (const float*)d_in[6];
    const float* Wv    = (const float*)d_in[7];
    const float* bv    = (const float*)d_in[8];
    const float* spd_w = (const float*)d_in[9];
    const float* gamma = (const float*)d_in[10];
    const float* beta  = (const float*)d_in[11];
    float* out = (float*)d_out;

    int n = in_sizes[0] / CC;   // 50000
    int e = in_sizes[1];        // 300000

    // one-time resources (created on the correctness call, before graph capture)
    static cudaStream_t s2 = nullptr;
    static cudaEvent_t evFork = nullptr, evJoin = nullptr;
    if (s2 == nullptr) {
        cudaStreamCreate(&s2);
        cudaEventCreateWithFlags(&evFork, cudaEventDisableTiming);
        cudaEventCreateWithFlags(&evJoin, cudaEventDisableTiming);
        cudaFuncSetAttribute(k_gemm_fused, cudaFuncAttributeMaxDynamicSharedMemorySize, GEMM_SMEM);
    }

    // main stream: GEMM chain
    k_cvt_w<<<(CC * CC + 255) / 256, 256>>>(Wq, Wk, Wv);                    // 1
    k_cvt_x<<<(n * CC / 4 + 255) / 256, 256>>>(x, n * CC / 4);              // 2

    // fork side stream: edge preprocessing chain
    cudaEventRecord(evFork, 0);
    cudaStreamWaitEvent(s2, evFork, 0);
    k_init<<<(n + 255) / 256, 256, 0, s2>>>(n);                             // 3
    k_gemm_fused<<<(n + 127) / 128, 256, GEMM_SMEM>>>(1, 4, n, 0, bk, bv);  // 4: K|V (ncu window)
    k_edge<<<256, 256, 0, s2>>>(src, dst, e);                               // 5
    k_bfs<<<1, 256, 0, s2>>>();                                             // 6
    k_scan<<<1, 256, 0, s2>>>();                                            // 7
    k_scatter<<<256, 256, 0, s2>>>(src, dst, e);                            // 8
    k_gemm_fused<<<2, 256, GEMM_SMEM>>>(0, 2, ND, 1, bq, bq);               // 9: Q
    cudaEventRecord(evJoin, s2);
    cudaStreamWaitEvent(0, evJoin, 0);

    // join: attention + layernorm on main stream
    k_attn<<<ND, 512>>>(spd_w);                                             // 10
    k_ln<<<(n + 7) / 8, 256>>>(x, gamma, beta, out, n);                     // 11
}